// round 4
// baseline (speedup 1.0000x reference)
#include <cuda_runtime.h>
#include <cstdint>
#include <math.h>

// ---------------------------------------------------------------------------
// Problem constants
// ---------------------------------------------------------------------------
#define Bn   8
#define Tn   4096
#define Dm   512
#define Ff   2048
#define Ee   8
#define NTOK (Bn*Tn)
#define NASG (NTOK*2)

// ---------------------------------------------------------------------------
// Scratch
// ---------------------------------------------------------------------------
__device__ int   g_cnt[Ee];
__device__ int   g_off[Ee];
__device__ int   g_fill[Ee];
__device__ int   g_rows[NASG];
__device__ float g_h[(size_t)NASG * Ff];           // 512 MB (tf32 bits)
__device__ float g_xc[(size_t)NTOK * Dm];          // 64 MB  x in tf32 bits
__device__ float g_w1c[(size_t)Ee * Dm * Ff];      // 33.5 MB W1 tf32 bits
__device__ float g_w2c[(size_t)Ee * Ff * Dm];      // 33.5 MB W2 tf32 bits

// ---------------------------------------------------------------------------
// Helpers
// ---------------------------------------------------------------------------
__device__ __forceinline__ uint32_t smem_u32(const void* p) {
    uint32_t a;
    asm("{ .reg .u64 t; cvta.to.shared.u64 t, %1; cvt.u32.u64 %0, t; }" : "=r"(a) : "l"(p));
    return a;
}
__device__ __forceinline__ float f2tf32f(float f) {
    uint32_t r;
    asm("cvt.rna.tf32.f32 %0, %1;" : "=r"(r) : "f"(f));
    return __uint_as_float(r);
}
__device__ __forceinline__ void mma_tf32(float* c, const uint32_t* a, const uint32_t* b) {
    asm volatile(
        "mma.sync.aligned.m16n8k8.row.col.f32.tf32.tf32.f32 "
        "{%0,%1,%2,%3},{%4,%5,%6,%7},{%8,%9},{%0,%1,%2,%3};"
        : "+f"(c[0]), "+f"(c[1]), "+f"(c[2]), "+f"(c[3])
        : "r"(a[0]), "r"(a[1]), "r"(a[2]), "r"(a[3]), "r"(b[0]), "r"(b[1]));
}
#define CP16(dst_u32, src_ptr) \
    asm volatile("cp.async.cg.shared.global [%0], [%1], 16;" :: "r"(dst_u32), "l"(src_ptr))
#define CP_COMMIT() asm volatile("cp.async.commit_group;" ::: "memory")
#define CP_WAIT(n)  asm volatile("cp.async.wait_group %0;" :: "n"(n) : "memory")

// ---------------------------------------------------------------------------
// Small kernels
// ---------------------------------------------------------------------------
__global__ void zero_and_reset(float4* __restrict__ out4, int n4) {
    int i = blockIdx.x * blockDim.x + threadIdx.x;
    int stride = gridDim.x * blockDim.x;
    float4 z = make_float4(0.f, 0.f, 0.f, 0.f);
    for (; i < n4; i += stride) out4[i] = z;
    if (blockIdx.x == 0 && threadIdx.x < Ee) {
        g_cnt[threadIdx.x]  = 0;
        g_fill[threadIdx.x] = 0;
    }
}

// elementwise tf32 (RNA) pre-conversion
__global__ void cvt_tf32_kernel(const float4* __restrict__ in, float4* __restrict__ out, int n4) {
    int i = blockIdx.x * blockDim.x + threadIdx.x;
    int stride = gridDim.x * blockDim.x;
    for (; i < n4; i += stride) {
        float4 v = in[i];
        v.x = f2tf32f(v.x); v.y = f2tf32f(v.y);
        v.z = f2tf32f(v.z); v.w = f2tf32f(v.w);
        out[i] = v;
    }
}

__global__ void route_kernel(const int* __restrict__ tok, float* __restrict__ eid) {
    int i = blockIdx.x * blockDim.x + threadIdx.x;
    if (i >= NTOK) return;
    int b = i >> 12;
    int base = b * Tn + tok[i];
    int e0 = base % Ee, e1 = (base + 1) % Ee;
    eid[2 * i]     = (float)e0;
    eid[2 * i + 1] = (float)e1;
    atomicAdd(&g_cnt[e0], 1);
    atomicAdd(&g_cnt[e1], 1);
}

__global__ void offsets_kernel(float* __restrict__ ecnt) {
    if (threadIdx.x == 0 && blockIdx.x == 0) {
        int s = 0;
        for (int e = 0; e < Ee; e++) { g_off[e] = s; ecnt[e] = (float)g_cnt[e]; s += g_cnt[e]; }
    }
}

__global__ void fill_kernel(const int* __restrict__ tok) {
    int i = blockIdx.x * blockDim.x + threadIdx.x;
    if (i >= NTOK) return;
    int b = i >> 12;
    int base = b * Tn + tok[i];
    int e0 = base % Ee, e1 = (base + 1) % Ee;
    int p0 = atomicAdd(&g_fill[e0], 1); g_rows[g_off[e0] + p0] = i;
    int p1 = atomicAdd(&g_fill[e1], 1); g_rows[g_off[e1] + p1] = i;
}

// ---------------------------------------------------------------------------
// mma.sync tf32 grouped GEMM.  Operands already tf32-rounded in gmem.
// Tile 128x128, BK=32, 256 threads = 8 warps (4m x 2n), warp tile 32x64.
// ---------------------------------------------------------------------------
#define A_STRIDE 36
#define B_STRIDE 132
#define A_ELEMS  (128 * A_STRIDE)
#define B_ELEMS  (32 * B_STRIDE)
#define SMEM_FLOATS (2 * (A_ELEMS + B_ELEMS))
#define SMEM_BYTES  (SMEM_FLOATS * 4)      /* 70656 */

template <bool G1>
__global__ __launch_bounds__(256, 2) void moe_gemm_mma(
    const float* __restrict__ Asrc,     // g_xc (G1) or g_h (!G1), tf32 bits
    const float* __restrict__ Bw,       // g_w1c / g_w2c: [E][K][N], tf32 bits
    const float* __restrict__ bias,     // b1 or b2 (f32)
    float* __restrict__ outp)           // g_h (G1) or out (!G1)
{
    constexpr int KTOT  = G1 ? Dm : Ff;
    constexpr int NFULL = G1 ? Ff : Dm;
    constexpr int NC    = KTOT / 32;

    const int e   = blockIdx.z;
    const int cnt = g_cnt[e];
    const int m0  = blockIdx.y * 128;
    if (m0 >= cnt) return;
    const int off = g_off[e];
    const int n0  = blockIdx.x * 128;
    const float* Bsrc = Bw + (size_t)e * KTOT * NFULL + n0 + (threadIdx.x & 31) * 4
                        + (size_t)(threadIdx.x >> 5) * NFULL;

    extern __shared__ float smem[];
    const uint32_t sb = smem_u32(smem);

    const int t = threadIdx.x;
    const int lane = t & 31, warp = t >> 5;
    const int wm = warp & 3, wn = warp >> 2;
    const int qr = lane >> 2, qc = lane & 3;

    // A gather pointers (persist; gathered rows)
    const float* aptr[4];
#pragma unroll
    for (int it = 0; it < 4; it++) {
        int gi = m0 + it * 32 + (t >> 3);
        if (gi >= cnt) gi = cnt - 1;
        size_t r = G1 ? (size_t)g_rows[off + gi] : (size_t)(off + gi);
        aptr[it] = Asrc + r * KTOT + (t & 7) * 4;
    }

    const uint32_t a_s0 = (uint32_t)((t >> 3) * A_STRIDE + (t & 7) * 4) * 4;
    const uint32_t b_s0 = (uint32_t)((t >> 5) * B_STRIDE + (t & 31) * 4) * 4;

    auto load_chunk = [&](int c) {
        const int buf = c & 1;
        const int k0  = c * 32;
        const uint32_t abase = sb + buf * (A_ELEMS * 4) + a_s0;
        const uint32_t bbase = sb + (2 * A_ELEMS + buf * B_ELEMS) * 4 + b_s0;
#pragma unroll
        for (int it = 0; it < 4; it++)
            CP16(abase + it * (32 * A_STRIDE * 4), aptr[it] + k0);
#pragma unroll
        for (int it = 0; it < 4; it++)
            CP16(bbase + it * (8 * B_STRIDE * 4), Bsrc + (size_t)(k0 + it * 8) * NFULL);
        CP_COMMIT();
    };

    float acc[2][8][4];
#pragma unroll
    for (int fm = 0; fm < 2; fm++)
#pragma unroll
        for (int fn = 0; fn < 8; fn++)
#pragma unroll
            for (int q = 0; q < 4; q++) acc[fm][fn][q] = 0.f;

    load_chunk(0);

    for (int c = 0; c < NC; c++) {
        if (c + 1 < NC) { load_chunk(c + 1); CP_WAIT(1); }
        else           { CP_WAIT(0); }
        __syncthreads();

        const float* A = smem + (c & 1) * A_ELEMS;
        const float* B = smem + 2 * A_ELEMS + (c & 1) * B_ELEMS;

#pragma unroll
        for (int ks = 0; ks < 4; ks++) {
            const int k = ks * 8;
            uint32_t a[2][4], b[8][2];
#pragma unroll
            for (int fm = 0; fm < 2; fm++) {
                int r = wm * 32 + fm * 16 + qr;
                a[fm][0] = __float_as_uint(A[r * A_STRIDE + k + qc]);
                a[fm][1] = __float_as_uint(A[(r + 8) * A_STRIDE + k + qc]);
                a[fm][2] = __float_as_uint(A[r * A_STRIDE + k + qc + 4]);
                a[fm][3] = __float_as_uint(A[(r + 8) * A_STRIDE + k + qc + 4]);
            }
#pragma unroll
            for (int fn = 0; fn < 8; fn++) {
                int col = wn * 64 + fn * 8 + qr;
                b[fn][0] = __float_as_uint(B[(k + qc) * B_STRIDE + col]);
                b[fn][1] = __float_as_uint(B[(k + qc + 4) * B_STRIDE + col]);
            }
#pragma unroll
            for (int fm = 0; fm < 2; fm++)
#pragma unroll
                for (int fn = 0; fn < 8; fn++)
                    mma_tf32(acc[fm][fn], a[fm], b[fn]);
        }
        __syncthreads();
    }

    // ---- epilogue ----
#pragma unroll
    for (int fm = 0; fm < 2; fm++) {
#pragma unroll
        for (int rr = 0; rr < 2; rr++) {
            int m = m0 + wm * 32 + fm * 16 + rr * 8 + qr;
            if (m >= cnt) continue;
            float* orow;
            if (G1) orow = outp + (size_t)(off + m) * Ff;
            else    orow = outp + (size_t)g_rows[off + m] * Dm;
#pragma unroll
            for (int fn = 0; fn < 8; fn++) {
                int col = n0 + wn * 64 + fn * 8 + 2 * qc;
                float v0 = acc[fm][fn][rr * 2 + 0] + bias[e * NFULL + col];
                float v1 = acc[fm][fn][rr * 2 + 1] + bias[e * NFULL + col + 1];
                if (G1) {
                    // gelu, then round to tf32 so GEMM2 needs no in-loop cvt
                    float2 g;
                    g.x = f2tf32f(0.5f * v0 * (1.0f + erff(v0 * 0.7071067811865476f)));
                    g.y = f2tf32f(0.5f * v1 * (1.0f + erff(v1 * 0.7071067811865476f)));
                    *(float2*)(orow + col) = g;
                } else {
                    atomicAdd(&orow[col],     0.25f * v0);
                    atomicAdd(&orow[col + 1], 0.25f * v1);
                }
            }
        }
    }
}

// ---------------------------------------------------------------------------
// Launch
// ---------------------------------------------------------------------------
extern "C" void kernel_launch(void* const* d_in, const int* in_sizes, int n_in,
                              void* d_out, int out_size) {
    const float* x   = (const float*)d_in[0];
    const int*   tok = (const int*)d_in[1];
    const float* W1  = (const float*)d_in[2];
    const float* b1  = (const float*)d_in[3];
    const float* W2  = (const float*)d_in[4];
    const float* b2  = (const float*)d_in[5];

    float* out  = (float*)d_out;
    float* eid  = out + (size_t)NTOK * Dm;
    float* ecnt = eid + (size_t)NASG;

    static bool attr_set = false;
    if (!attr_set) {
        cudaFuncSetAttribute(moe_gemm_mma<true>,  cudaFuncAttributeMaxDynamicSharedMemorySize, SMEM_BYTES);
        cudaFuncSetAttribute(moe_gemm_mma<false>, cudaFuncAttributeMaxDynamicSharedMemorySize, SMEM_BYTES);
        attr_set = true;
    }

    float* hbuf; cudaGetSymbolAddress((void**)&hbuf, g_h);
    float* xc;   cudaGetSymbolAddress((void**)&xc,   g_xc);
    float* w1c;  cudaGetSymbolAddress((void**)&w1c,  g_w1c);
    float* w2c;  cudaGetSymbolAddress((void**)&w2c,  g_w2c);

    int n4 = (NTOK * Dm) / 4;
    zero_and_reset<<<4096, 256>>>((float4*)out, n4);
    route_kernel<<<NTOK / 256, 256>>>(tok, eid);
    offsets_kernel<<<1, 32>>>(ecnt);
    fill_kernel<<<NTOK / 256, 256>>>(tok);

    // tf32 pre-conversions
    cvt_tf32_kernel<<<2048, 256>>>((const float4*)x,  (float4*)xc,  (NTOK * Dm) / 4);
    cvt_tf32_kernel<<<2048, 256>>>((const float4*)W1, (float4*)w1c, (Ee * Dm * Ff) / 4);
    cvt_tf32_kernel<<<2048, 256>>>((const float4*)W2, (float4*)w2c, (Ee * Ff * Dm) / 4);

    dim3 g1(Ff / 128, 96, Ee);
    moe_gemm_mma<true><<<g1, 256, SMEM_BYTES>>>(xc, w1c, b1, hbuf);
    dim3 g2(Dm / 128, 96, Ee);
    moe_gemm_mma<false><<<g2, 256, SMEM_BYTES>>>(hbuf, w2c, b2, out);
}

// round 5
// speedup vs baseline: 1.1446x; 1.1446x over previous
#include <cuda_runtime.h>
#include <cuda_fp16.h>
#include <cstdint>
#include <math.h>

// ---------------------------------------------------------------------------
// Problem constants
// ---------------------------------------------------------------------------
#define Bn   8
#define Tn   4096
#define Dm   512
#define Ff   2048
#define Ee   8
#define NTOK (Bn*Tn)
#define NASG (NTOK*2)

// ---------------------------------------------------------------------------
// Scratch
// ---------------------------------------------------------------------------
__device__ int    g_cnt[Ee];
__device__ int    g_off[Ee];
__device__ int    g_fill[Ee];
__device__ int    g_rows[NASG];
__device__ __half g_h[(size_t)NASG * Ff];            // 256 MB intermediate (fp16)
__device__ __half g_xh[(size_t)NTOK * Dm];           // 33.5 MB x (fp16)
__device__ __half g_w1t[(size_t)Ee * Ff * Dm];       // 16.8 MB W1^T [E][F][D] (fp16)
__device__ __half g_w2t[(size_t)Ee * Dm * Ff];       // 16.8 MB W2^T [E][D][F] (fp16)

// ---------------------------------------------------------------------------
// Helpers
// ---------------------------------------------------------------------------
__device__ __forceinline__ uint32_t smem_u32(const void* p) {
    uint32_t a;
    asm("{ .reg .u64 t; cvta.to.shared.u64 t, %1; cvt.u32.u64 %0, t; }" : "=r"(a) : "l"(p));
    return a;
}
__device__ __forceinline__ void mma_f16(float* c, const uint32_t* a, const uint32_t* b) {
    asm volatile(
        "mma.sync.aligned.m16n8k16.row.col.f32.f16.f16.f32 "
        "{%0,%1,%2,%3},{%4,%5,%6,%7},{%8,%9},{%0,%1,%2,%3};"
        : "+f"(c[0]), "+f"(c[1]), "+f"(c[2]), "+f"(c[3])
        : "r"(a[0]), "r"(a[1]), "r"(a[2]), "r"(a[3]), "r"(b[0]), "r"(b[1]));
}
#define CP16(dst_u32, src_ptr) \
    asm volatile("cp.async.cg.shared.global [%0], [%1], 16;" :: "r"(dst_u32), "l"(src_ptr))
#define CP_COMMIT() asm volatile("cp.async.commit_group;" ::: "memory")
#define CP_WAIT(n)  asm volatile("cp.async.wait_group %0;" :: "n"(n) : "memory")

// ---------------------------------------------------------------------------
// Small kernels
// ---------------------------------------------------------------------------
__global__ void zero_and_reset(float4* __restrict__ out4, int n4) {
    int i = blockIdx.x * blockDim.x + threadIdx.x;
    int stride = gridDim.x * blockDim.x;
    float4 z = make_float4(0.f, 0.f, 0.f, 0.f);
    for (; i < n4; i += stride) out4[i] = z;
    if (blockIdx.x == 0 && threadIdx.x < Ee) {
        g_cnt[threadIdx.x]  = 0;
        g_fill[threadIdx.x] = 0;
    }
}

// x (f32) -> fp16
__global__ void cvt_f16_kernel(const float4* __restrict__ in, __half2* __restrict__ out, int n4) {
    int i = blockIdx.x * blockDim.x + threadIdx.x;
    int stride = gridDim.x * blockDim.x;
    for (; i < n4; i += stride) {
        float4 v = in[i];
        out[2 * i]     = __floats2half2_rn(v.x, v.y);
        out[2 * i + 1] = __floats2half2_rn(v.z, v.w);
    }
}

// out[e][c][r] = (half)in[e][r][c];  grid (C/32, R/32, E), block (32,8)
__global__ void transpose_f16_kernel(const float* __restrict__ in, __half* __restrict__ out,
                                     int R, int C) {
    __shared__ float tile[32][33];
    int e = blockIdx.z;
    const float* src = in + (size_t)e * R * C;
    __half* dst = out + (size_t)e * R * C;
    int x = blockIdx.x * 32 + threadIdx.x;
#pragma unroll
    for (int i = threadIdx.y; i < 32; i += 8) {
        int y = blockIdx.y * 32 + i;
        tile[i][threadIdx.x] = src[(size_t)y * C + x];
    }
    __syncthreads();
    int xo = blockIdx.y * 32 + threadIdx.x;
#pragma unroll
    for (int i = threadIdx.y; i < 32; i += 8) {
        int yo = blockIdx.x * 32 + i;
        dst[(size_t)yo * R + xo] = __float2half_rn(tile[threadIdx.x][i]);
    }
}

__global__ void route_kernel(const int* __restrict__ tok, float* __restrict__ eid) {
    int i = blockIdx.x * blockDim.x + threadIdx.x;
    if (i >= NTOK) return;
    int b = i >> 12;
    int base = b * Tn + tok[i];
    int e0 = base % Ee, e1 = (base + 1) % Ee;
    eid[2 * i]     = (float)e0;
    eid[2 * i + 1] = (float)e1;
    atomicAdd(&g_cnt[e0], 1);
    atomicAdd(&g_cnt[e1], 1);
}

__global__ void offsets_kernel(float* __restrict__ ecnt) {
    if (threadIdx.x == 0 && blockIdx.x == 0) {
        int s = 0;
        for (int e = 0; e < Ee; e++) { g_off[e] = s; ecnt[e] = (float)g_cnt[e]; s += g_cnt[e]; }
    }
}

__global__ void fill_kernel(const int* __restrict__ tok) {
    int i = blockIdx.x * blockDim.x + threadIdx.x;
    if (i >= NTOK) return;
    int b = i >> 12;
    int base = b * Tn + tok[i];
    int e0 = base % Ee, e1 = (base + 1) % Ee;
    int p0 = atomicAdd(&g_fill[e0], 1); g_rows[g_off[e0] + p0] = i;
    int p1 = atomicAdd(&g_fill[e1], 1); g_rows[g_off[e1] + p1] = i;
}

// ---------------------------------------------------------------------------
// fp16 mma.sync grouped GEMM.
// Tile 128x128, BK=32, 256 threads = 8 warps (4m x 2n), warp tile 32x64.
// A smem [128 m][40 halves]; B smem [128 n][40 halves] (B pre-transposed [N][K]).
// Stride 40 halves -> fragment half2 reads are conflict-free (verified mapping).
// ---------------------------------------------------------------------------
#define TSTR  40                       /* halves per smem row */
#define TILE_H (128 * TSTR)            /* 5120 halves = 10240 B per tile */

template <bool G1>
__global__ __launch_bounds__(256, 2) void moe_gemm_f16(
    const __half* __restrict__ Asrc,    // g_xh (G1) or g_h (!G1)
    const __half* __restrict__ Bt,      // g_w1t / g_w2t: [E][N][K]
    const float*  __restrict__ bias,    // b1 or b2 (f32)
    void*         __restrict__ outp)    // g_h (G1, half) or out (!G1, float)
{
    constexpr int KTOT  = G1 ? Dm : Ff;      // 512 / 2048
    constexpr int NFULL = G1 ? Ff : Dm;      // 2048 / 512
    constexpr int NC    = KTOT / 32;

    const int e   = blockIdx.z;
    const int cnt = g_cnt[e];
    const int m0  = blockIdx.y * 128;
    if (m0 >= cnt) return;
    const int off = g_off[e];
    const int n0  = blockIdx.x * 128;

    __shared__ __half As[2][TILE_H];
    __shared__ __half Bs[2][TILE_H];

    const int t = threadIdx.x;
    const int lane = t & 31, warp = t >> 5;
    const int wm = warp & 3, wn = warp >> 2;
    const int qr = lane >> 2, qc = lane & 3;

    // ---- loaders: thread t covers rows {t>>2, 64+(t>>2)}, 8-half group t&3 ----
    const int lrow = t >> 2, lc8 = (t & 3) * 8;

    const __half* aptr[2];
#pragma unroll
    for (int it = 0; it < 2; it++) {
        int gi = m0 + it * 64 + lrow;
        if (gi >= cnt) gi = cnt - 1;
        size_t r = G1 ? (size_t)g_rows[off + gi] : (size_t)(off + gi);
        aptr[it] = Asrc + r * KTOT + lc8;
    }
    const __half* bptr[2];
#pragma unroll
    for (int it = 0; it < 2; it++)
        bptr[it] = Bt + ((size_t)e * NFULL + n0 + it * 64 + lrow) * KTOT + lc8;

    uint32_t adst[2], bdst[2];
    {
        uint32_t so = (uint32_t)(lrow * TSTR + lc8) * 2;
#pragma unroll
        for (int buf = 0; buf < 2; buf++) {
            adst[buf] = smem_u32(&As[buf][0]) + so;
            bdst[buf] = smem_u32(&Bs[buf][0]) + so;
        }
    }
    const uint32_t rowskip = 64 * TSTR * 2;   // bytes for 64 rows

    auto load_chunk = [&](int c) {
        const int buf = c & 1;
        const int k0  = c * 32;
        CP16(adst[buf],           aptr[0] + k0);
        CP16(adst[buf] + rowskip, aptr[1] + k0);
        CP16(bdst[buf],           bptr[0] + k0);
        CP16(bdst[buf] + rowskip, bptr[1] + k0);
        CP_COMMIT();
    };

    float acc[2][8][4];
#pragma unroll
    for (int fm = 0; fm < 2; fm++)
#pragma unroll
        for (int fn = 0; fn < 8; fn++)
#pragma unroll
            for (int q = 0; q < 4; q++) acc[fm][fn][q] = 0.f;

    load_chunk(0);

    for (int c = 0; c < NC; c++) {
        if (c + 1 < NC) { load_chunk(c + 1); CP_WAIT(1); }
        else           { CP_WAIT(0); }
        __syncthreads();

        const __half* A = As[c & 1];
        const __half* B = Bs[c & 1];

#pragma unroll
        for (int ks = 0; ks < 2; ks++) {
            const int k = ks * 16 + qc * 2;
            uint32_t a[2][4], b[8][2];
#pragma unroll
            for (int fm = 0; fm < 2; fm++) {
                int r = wm * 32 + fm * 16 + qr;
                a[fm][0] = *(const uint32_t*)(A + r * TSTR + k);
                a[fm][1] = *(const uint32_t*)(A + (r + 8) * TSTR + k);
                a[fm][2] = *(const uint32_t*)(A + r * TSTR + k + 8);
                a[fm][3] = *(const uint32_t*)(A + (r + 8) * TSTR + k + 8);
            }
#pragma unroll
            for (int fn = 0; fn < 8; fn++) {
                int n = wn * 64 + fn * 8 + qr;
                b[fn][0] = *(const uint32_t*)(B + n * TSTR + k);
                b[fn][1] = *(const uint32_t*)(B + n * TSTR + k + 8);
            }
#pragma unroll
            for (int fm = 0; fm < 2; fm++)
#pragma unroll
                for (int fn = 0; fn < 8; fn++)
                    mma_f16(acc[fm][fn], a[fm], b[fn]);
        }
        __syncthreads();
    }

    // ---- epilogue ----
#pragma unroll
    for (int fm = 0; fm < 2; fm++) {
#pragma unroll
        for (int rr = 0; rr < 2; rr++) {
            int m = m0 + wm * 32 + fm * 16 + rr * 8 + qr;
            if (m >= cnt) continue;
#pragma unroll
            for (int fn = 0; fn < 8; fn++) {
                int col = n0 + wn * 64 + fn * 8 + 2 * qc;
                float v0 = acc[fm][fn][rr * 2 + 0] + bias[e * NFULL + col];
                float v1 = acc[fm][fn][rr * 2 + 1] + bias[e * NFULL + col + 1];
                if (G1) {
                    __half* orow = (__half*)outp + (size_t)(off + m) * Ff;
                    float g0 = 0.5f * v0 * (1.0f + erff(v0 * 0.7071067811865476f));
                    float g1 = 0.5f * v1 * (1.0f + erff(v1 * 0.7071067811865476f));
                    *(__half2*)(orow + col) = __floats2half2_rn(g0, g1);
                } else {
                    float* orow = (float*)outp + (size_t)g_rows[off + m] * Dm;
                    atomicAdd(&orow[col],     0.25f * v0);
                    atomicAdd(&orow[col + 1], 0.25f * v1);
                }
            }
        }
    }
}

// ---------------------------------------------------------------------------
// Launch
// ---------------------------------------------------------------------------
extern "C" void kernel_launch(void* const* d_in, const int* in_sizes, int n_in,
                              void* d_out, int out_size) {
    const float* x   = (const float*)d_in[0];
    const int*   tok = (const int*)d_in[1];
    const float* W1  = (const float*)d_in[2];
    const float* b1  = (const float*)d_in[3];
    const float* W2  = (const float*)d_in[4];
    const float* b2  = (const float*)d_in[5];

    float* out  = (float*)d_out;
    float* eid  = out + (size_t)NTOK * Dm;
    float* ecnt = eid + (size_t)NASG;

    __half* hbuf; cudaGetSymbolAddress((void**)&hbuf, g_h);
    __half* xh;   cudaGetSymbolAddress((void**)&xh,   g_xh);
    __half* w1t;  cudaGetSymbolAddress((void**)&w1t,  g_w1t);
    __half* w2t;  cudaGetSymbolAddress((void**)&w2t,  g_w2t);

    int n4 = (NTOK * Dm) / 4;
    zero_and_reset<<<4096, 256>>>((float4*)out, n4);
    route_kernel<<<NTOK / 256, 256>>>(tok, eid);
    offsets_kernel<<<1, 32>>>(ecnt);
    fill_kernel<<<NTOK / 256, 256>>>(tok);

    // fp16 prep
    cvt_f16_kernel<<<1024, 256>>>((const float4*)x, (__half2*)xh, (NTOK * Dm) / 4);
    dim3 tb(32, 8);
    transpose_f16_kernel<<<dim3(Ff / 32, Dm / 32, Ee), tb>>>(W1, w1t, Dm, Ff); // [D,F]->[F,D]
    transpose_f16_kernel<<<dim3(Dm / 32, Ff / 32, Ee), tb>>>(W2, w2t, Ff, Dm); // [F,D]->[D,F]

    dim3 g1(Ff / 128, 96, Ee);
    moe_gemm_f16<true><<<g1, 256>>>(xh, w1t, b1, (void*)hbuf);
    dim3 g2(Dm / 128, 96, Ee);
    moe_gemm_f16<false><<<g2, 256>>>(hbuf, w2t, b2, (void*)out);
}

// round 7
// speedup vs baseline: 1.1694x; 1.0217x over previous
#include <cuda_runtime.h>
#include <cuda_fp16.h>
#include <cstdint>
#include <math.h>

// ---------------------------------------------------------------------------
// Problem constants
// ---------------------------------------------------------------------------
#define Bn   8
#define Tn   4096
#define Dm   512
#define Ff   2048
#define Ee   8
#define NTOK (Bn*Tn)
#define NASG (NTOK*2)

// ---------------------------------------------------------------------------
// Scratch
// ---------------------------------------------------------------------------
__device__ int    g_cnt[Ee];
__device__ int    g_off[Ee];
__device__ int    g_fill[Ee];
__device__ int    g_rows[NASG];
__device__ __half g_h[(size_t)NASG * Ff];            // 256 MB intermediate (fp16)
__device__ __half g_xh[(size_t)NTOK * Dm];           // 33.5 MB x (fp16)
__device__ __half g_w1t[(size_t)Ee * Ff * Dm];       // 16.8 MB W1^T [E][F][D]
__device__ __half g_w2t[(size_t)Ee * Dm * Ff];       // 16.8 MB W2^T [E][D][F]

// ---------------------------------------------------------------------------
// Helpers
// ---------------------------------------------------------------------------
__device__ __forceinline__ uint32_t smem_u32(const void* p) {
    uint32_t a;
    asm("{ .reg .u64 t; cvta.to.shared.u64 t, %1; cvt.u32.u64 %0, t; }" : "=r"(a) : "l"(p));
    return a;
}
__device__ __forceinline__ void mma_f16(float* c, const uint32_t* a, const uint32_t* b) {
    asm volatile(
        "mma.sync.aligned.m16n8k16.row.col.f32.f16.f16.f32 "
        "{%0,%1,%2,%3},{%4,%5,%6,%7},{%8,%9},{%0,%1,%2,%3};"
        : "+f"(c[0]), "+f"(c[1]), "+f"(c[2]), "+f"(c[3])
        : "r"(a[0]), "r"(a[1]), "r"(a[2]), "r"(a[3]), "r"(b[0]), "r"(b[1]));
}
#define CP16(dst_u32, src_ptr) \
    asm volatile("cp.async.cg.shared.global [%0], [%1], 16;" :: "r"(dst_u32), "l"(src_ptr))
#define CP_COMMIT() asm volatile("cp.async.commit_group;" ::: "memory")
#define CP_WAIT(n)  asm volatile("cp.async.wait_group %0;" :: "n"(n) : "memory")

// ---------------------------------------------------------------------------
// Small kernels
// ---------------------------------------------------------------------------
__global__ void zero_and_reset(float4* __restrict__ out4, int n4) {
    int i = blockIdx.x * blockDim.x + threadIdx.x;
    int stride = gridDim.x * blockDim.x;
    float4 z = make_float4(0.f, 0.f, 0.f, 0.f);
    for (; i < n4; i += stride) out4[i] = z;
    if (blockIdx.x == 0 && threadIdx.x < Ee) {
        g_cnt[threadIdx.x]  = 0;
        g_fill[threadIdx.x] = 0;
    }
}

__global__ void cvt_f16_kernel(const float4* __restrict__ in, __half2* __restrict__ out, int n4) {
    int i = blockIdx.x * blockDim.x + threadIdx.x;
    int stride = gridDim.x * blockDim.x;
    for (; i < n4; i += stride) {
        float4 v = in[i];
        out[2 * i]     = __floats2half2_rn(v.x, v.y);
        out[2 * i + 1] = __floats2half2_rn(v.z, v.w);
    }
}

__global__ void transpose_f16_kernel(const float* __restrict__ in, __half* __restrict__ out,
                                     int R, int C) {
    __shared__ float tile[32][33];
    int e = blockIdx.z;
    const float* src = in + (size_t)e * R * C;
    __half* dst = out + (size_t)e * R * C;
    int x = blockIdx.x * 32 + threadIdx.x;
#pragma unroll
    for (int i = threadIdx.y; i < 32; i += 8) {
        int y = blockIdx.y * 32 + i;
        tile[i][threadIdx.x] = src[(size_t)y * C + x];
    }
    __syncthreads();
    int xo = blockIdx.y * 32 + threadIdx.x;
#pragma unroll
    for (int i = threadIdx.y; i < 32; i += 8) {
        int yo = blockIdx.x * 32 + i;
        dst[(size_t)yo * R + xo] = __float2half_rn(tile[threadIdx.x][i]);
    }
}

__global__ void route_kernel(const int* __restrict__ tok, float* __restrict__ eid) {
    int i = blockIdx.x * blockDim.x + threadIdx.x;
    if (i >= NTOK) return;
    int b = i >> 12;
    int base = b * Tn + tok[i];
    int e0 = base % Ee, e1 = (base + 1) % Ee;
    eid[2 * i]     = (float)e0;
    eid[2 * i + 1] = (float)e1;
    atomicAdd(&g_cnt[e0], 1);
    atomicAdd(&g_cnt[e1], 1);
}

__global__ void offsets_kernel(float* __restrict__ ecnt) {
    if (threadIdx.x == 0 && blockIdx.x == 0) {
        int s = 0;
        for (int e = 0; e < Ee; e++) { g_off[e] = s; ecnt[e] = (float)g_cnt[e]; s += g_cnt[e]; }
    }
}

__global__ void fill_kernel(const int* __restrict__ tok) {
    int i = blockIdx.x * blockDim.x + threadIdx.x;
    if (i >= NTOK) return;
    int b = i >> 12;
    int base = b * Tn + tok[i];
    int e0 = base % Ee, e1 = (base + 1) % Ee;
    int p0 = atomicAdd(&g_fill[e0], 1); g_rows[g_off[e0] + p0] = i;
    int p1 = atomicAdd(&g_fill[e1], 1); g_rows[g_off[e1] + p1] = i;
}

// ---------------------------------------------------------------------------
// fp16 mma.sync grouped GEMM, 4-stage cp.async pipeline, 1 sync per chunk.
// Correct drain: allowed-pending at iter c = min(NC-1-c, 2).
// Tile 128x128, BK=32, 256 threads = 8 warps (4m x 2n), warp tile 32x64.
// ---------------------------------------------------------------------------
#define TSTR   40
#define TILE_H (128 * TSTR)
#define NSTAGE 4
#define SMEM_BYTES (NSTAGE * 2 * TILE_H * 2)   /* 81920 B */

template <bool G1>
__global__ __launch_bounds__(256, 2) void moe_gemm_f16(
    const __half* __restrict__ Asrc,
    const __half* __restrict__ Bt,      // [E][N][K]
    const float*  __restrict__ bias,
    void*         __restrict__ outp)
{
    constexpr int KTOT  = G1 ? Dm : Ff;
    constexpr int NFULL = G1 ? Ff : Dm;
    constexpr int NC    = KTOT / 32;

    const int e   = blockIdx.z;
    const int cnt = g_cnt[e];
    const int m0  = blockIdx.y * 128;
    if (m0 >= cnt) return;
    const int off = g_off[e];
    const int n0  = blockIdx.x * 128;

    extern __shared__ __half sm[];
    __half* Asm = sm;                       // [NSTAGE][TILE_H]
    __half* Bsm = sm + NSTAGE * TILE_H;     // [NSTAGE][TILE_H]

    const int t = threadIdx.x;
    const int lane = t & 31, warp = t >> 5;
    const int wm = warp & 3, wn = warp >> 2;
    const int qr = lane >> 2, qc = lane & 3;

    const int lrow = t >> 2, lc8 = (t & 3) * 8;

    const __half* aptr[2];
#pragma unroll
    for (int it = 0; it < 2; it++) {
        int gi = m0 + it * 64 + lrow;
        if (gi >= cnt) gi = cnt - 1;
        size_t r = G1 ? (size_t)g_rows[off + gi] : (size_t)(off + gi);
        aptr[it] = Asrc + r * KTOT + lc8;
    }
    const __half* bptr[2];
#pragma unroll
    for (int it = 0; it < 2; it++)
        bptr[it] = Bt + ((size_t)e * NFULL + n0 + it * 64 + lrow) * KTOT + lc8;

    const uint32_t so = (uint32_t)(lrow * TSTR + lc8) * 2;
    const uint32_t a0 = smem_u32(Asm) + so;
    const uint32_t b0 = smem_u32(Bsm) + so;
    const uint32_t rowskip = 64 * TSTR * 2;

    auto load_chunk = [&](int c) {
        const uint32_t sbo = (uint32_t)(c & (NSTAGE - 1)) * (TILE_H * 2);
        const int k0 = c * 32;
        CP16(a0 + sbo,           aptr[0] + k0);
        CP16(a0 + sbo + rowskip, aptr[1] + k0);
        CP16(b0 + sbo,           bptr[0] + k0);
        CP16(b0 + sbo + rowskip, bptr[1] + k0);
        CP_COMMIT();
    };

    float acc[2][8][4];
#pragma unroll
    for (int fm = 0; fm < 2; fm++)
#pragma unroll
        for (int fn = 0; fn < 8; fn++)
#pragma unroll
            for (int q = 0; q < 4; q++) acc[fm][fn][q] = 0.f;

    // prologue: 3 chunks in flight
    load_chunk(0);
    load_chunk(1);
    load_chunk(2);

    for (int c = 0; c < NC; c++) {
        // Drain-correct wait: groups issued before this wait = min(NC, c+3);
        // to guarantee chunk c landed, allow pending = min(NC-1-c, 2).
        if (c <= NC - 3)      { CP_WAIT(2); }
        else if (c == NC - 2) { CP_WAIT(1); }
        else                  { CP_WAIT(0); }
        __syncthreads();         // all warps done with compute(c-1); stage (c-1)&3 free
        if (c + 3 < NC) load_chunk(c + 3);

        const __half* A = Asm + (c & (NSTAGE - 1)) * TILE_H;
        const __half* B = Bsm + (c & (NSTAGE - 1)) * TILE_H;

#pragma unroll
        for (int ks = 0; ks < 2; ks++) {
            const int k = ks * 16 + qc * 2;
            uint32_t a[2][4], b[8][2];
#pragma unroll
            for (int fm = 0; fm < 2; fm++) {
                int r = wm * 32 + fm * 16 + qr;
                a[fm][0] = *(const uint32_t*)(A + r * TSTR + k);
                a[fm][1] = *(const uint32_t*)(A + (r + 8) * TSTR + k);
                a[fm][2] = *(const uint32_t*)(A + r * TSTR + k + 8);
                a[fm][3] = *(const uint32_t*)(A + (r + 8) * TSTR + k + 8);
            }
#pragma unroll
            for (int fn = 0; fn < 8; fn++) {
                int n = wn * 64 + fn * 8 + qr;
                b[fn][0] = *(const uint32_t*)(B + n * TSTR + k);
                b[fn][1] = *(const uint32_t*)(B + n * TSTR + k + 8);
            }
#pragma unroll
            for (int fm = 0; fm < 2; fm++)
#pragma unroll
                for (int fn = 0; fn < 8; fn++)
                    mma_f16(acc[fm][fn], a[fm], b[fn]);
        }
    }

    // ---- epilogue ----
#pragma unroll
    for (int fm = 0; fm < 2; fm++) {
#pragma unroll
        for (int rr = 0; rr < 2; rr++) {
            int m = m0 + wm * 32 + fm * 16 + rr * 8 + qr;
            if (m >= cnt) continue;
#pragma unroll
            for (int fn = 0; fn < 8; fn++) {
                int col = n0 + wn * 64 + fn * 8 + 2 * qc;
                float v0 = acc[fm][fn][rr * 2 + 0] + bias[e * NFULL + col];
                float v1 = acc[fm][fn][rr * 2 + 1] + bias[e * NFULL + col + 1];
                if (G1) {
                    __half* orow = (__half*)outp + (size_t)(off + m) * Ff;
                    float g0 = 0.5f * v0 * (1.0f + erff(v0 * 0.7071067811865476f));
                    float g1 = 0.5f * v1 * (1.0f + erff(v1 * 0.7071067811865476f));
                    *(__half2*)(orow + col) = __floats2half2_rn(g0, g1);
                } else {
                    float* orow = (float*)outp + (size_t)g_rows[off + m] * Dm;
                    atomicAdd(&orow[col],     0.25f * v0);
                    atomicAdd(&orow[col + 1], 0.25f * v1);
                }
            }
        }
    }
}

// ---------------------------------------------------------------------------
// Launch
// ---------------------------------------------------------------------------
extern "C" void kernel_launch(void* const* d_in, const int* in_sizes, int n_in,
                              void* d_out, int out_size) {
    const float* x   = (const float*)d_in[0];
    const int*   tok = (const int*)d_in[1];
    const float* W1  = (const float*)d_in[2];
    const float* b1  = (const float*)d_in[3];
    const float* W2  = (const float*)d_in[4];
    const float* b2  = (const float*)d_in[5];

    float* out  = (float*)d_out;
    float* eid  = out + (size_t)NTOK * Dm;
    float* ecnt = eid + (size_t)NASG;

    static bool attr_set = false;
    if (!attr_set) {
        cudaFuncSetAttribute(moe_gemm_f16<true>,  cudaFuncAttributeMaxDynamicSharedMemorySize, SMEM_BYTES);
        cudaFuncSetAttribute(moe_gemm_f16<false>, cudaFuncAttributeMaxDynamicSharedMemorySize, SMEM_BYTES);
        attr_set = true;
    }

    __half* hbuf; cudaGetSymbolAddress((void**)&hbuf, g_h);
    __half* xh;   cudaGetSymbolAddress((void**)&xh,   g_xh);
    __half* w1t;  cudaGetSymbolAddress((void**)&w1t,  g_w1t);
    __half* w2t;  cudaGetSymbolAddress((void**)&w2t,  g_w2t);

    int n4 = (NTOK * Dm) / 4;
    zero_and_reset<<<4096, 256>>>((float4*)out, n4);
    route_kernel<<<NTOK / 256, 256>>>(tok, eid);
    offsets_kernel<<<1, 32>>>(ecnt);
    fill_kernel<<<NTOK / 256, 256>>>(tok);

    cvt_f16_kernel<<<1024, 256>>>((const float4*)x, (__half2*)xh, (NTOK * Dm) / 4);
    dim3 tb(32, 8);
    transpose_f16_kernel<<<dim3(Ff / 32, Dm / 32, Ee), tb>>>(W1, w1t, Dm, Ff);
    transpose_f16_kernel<<<dim3(Dm / 32, Ff / 32, Ee), tb>>>(W2, w2t, Ff, Dm);

    dim3 g1(Ff / 128, 96, Ee);
    moe_gemm_f16<true><<<g1, 256, SMEM_BYTES>>>(xh, w1t, b1, (void*)hbuf);
    dim3 g2(Dm / 128, 96, Ee);
    moe_gemm_f16<false><<<g2, 256, SMEM_BYTES>>>(hbuf, w2t, b2, (void*)out);
}

// round 10
// speedup vs baseline: 1.9097x; 1.6330x over previous
#include <cuda_runtime.h>
#include <cuda_fp16.h>
#include <cstdint>
#include <math.h>

// ---------------------------------------------------------------------------
// Problem constants
// ---------------------------------------------------------------------------
#define Bn   8
#define Tn   4096
#define Dm   512
#define Ff   2048
#define Ee   8
#define NTOK (Bn*Tn)
#define NASG (NTOK*2)

// ---------------------------------------------------------------------------
// Scratch
// ---------------------------------------------------------------------------
__device__ int    g_cnt[Ee];
__device__ int    g_off[Ee];
__device__ int    g_rows[NASG];
__device__ __half g_h[(size_t)NASG * Ff];            // 256 MB intermediate
__device__ __half g_xh[(size_t)NTOK * Dm];           // 33.5 MB x (fp16)
__device__ __half g_w1t[(size_t)Ee * Ff * Dm];       // W1^T [E][F][D]
__device__ __half g_w2t[(size_t)Ee * Dm * Ff];       // W2^T [E][D][F]

// ---------------------------------------------------------------------------
// Helpers
// ---------------------------------------------------------------------------
__device__ __forceinline__ uint32_t smem_u32(const void* p) {
    uint32_t a;
    asm("{ .reg .u64 t; cvta.to.shared.u64 t, %1; cvt.u32.u64 %0, t; }" : "=r"(a) : "l"(p));
    return a;
}
__device__ __forceinline__ void mma_f16(float* c, const uint32_t* a, const uint32_t* b) {
    asm volatile(
        "mma.sync.aligned.m16n8k16.row.col.f32.f16.f16.f32 "
        "{%0,%1,%2,%3},{%4,%5,%6,%7},{%8,%9},{%0,%1,%2,%3};"
        : "+f"(c[0]), "+f"(c[1]), "+f"(c[2]), "+f"(c[3])
        : "r"(a[0]), "r"(a[1]), "r"(a[2]), "r"(a[3]), "r"(b[0]), "r"(b[1]));
}
__device__ __forceinline__ void ldsm_x4(uint32_t& r0, uint32_t& r1, uint32_t& r2, uint32_t& r3,
                                        uint32_t addr) {
    asm volatile("ldmatrix.sync.aligned.m8n8.x4.shared.b16 {%0,%1,%2,%3}, [%4];"
                 : "=r"(r0), "=r"(r1), "=r"(r2), "=r"(r3) : "r"(addr));
}
#define CP16(dst_u32, src_ptr) \
    asm volatile("cp.async.cg.shared.global [%0], [%1], 16;" :: "r"(dst_u32), "l"(src_ptr))
#define CP_COMMIT() asm volatile("cp.async.commit_group;" ::: "memory")
#define CP_WAIT(n)  asm volatile("cp.async.wait_group %0;" :: "n"(n) : "memory")

// ---------------------------------------------------------------------------
// Prep: routing ids + histogram + offsets + gather lists, ONE block.
// Warp-private histograms (registers) + warp-ballot slot allocation: no
// cross-warp atomics. Any within-expert ordering of g_rows is valid.
// ---------------------------------------------------------------------------
__global__ __launch_bounds__(1024, 1) void prep_kernel(
    const int* __restrict__ tok, float* __restrict__ eid, float* __restrict__ ecnt)
{
    __shared__ int wh[32][8];        // per-warp histograms
    __shared__ int wbase[32][8];     // per-warp per-expert base slots
    const int t = threadIdx.x, lane = t & 31, w = t >> 5;

    // phase 1: per-lane counts (static-indexed -> registers)
    int c0=0,c1=0,c2=0,c3=0,c4=0,c5=0,c6=0,c7=0;
    for (int i = t; i < NTOK; i += 1024) {
        int b = i >> 12;
        int base = b * Tn + tok[i];
        int e0 = base & 7, e1 = (base + 1) & 7;
        eid[2 * i]     = (float)e0;
        eid[2 * i + 1] = (float)e1;
        c0 += (e0==0)+(e1==0); c1 += (e0==1)+(e1==1);
        c2 += (e0==2)+(e1==2); c3 += (e0==3)+(e1==3);
        c4 += (e0==4)+(e1==4); c5 += (e0==5)+(e1==5);
        c6 += (e0==6)+(e1==6); c7 += (e0==7)+(e1==7);
    }
    int cc[8] = {c0,c1,c2,c3,c4,c5,c6,c7};
#pragma unroll
    for (int e = 0; e < 8; e++) {
#pragma unroll
        for (int s = 16; s > 0; s >>= 1)
            cc[e] += __shfl_down_sync(0xFFFFFFFFu, cc[e], s);
    }
    if (lane == 0) {
#pragma unroll
        for (int e = 0; e < 8; e++) wh[w][e] = cc[e];
    }
    __syncthreads();

    // expert totals + offsets (thread 0), then per-warp bases (threads 0..255)
    __shared__ int s_off[8];
    if (t == 0) {
        int tot[8], s = 0;
#pragma unroll
        for (int e = 0; e < 8; e++) { tot[e] = 0; for (int ww = 0; ww < 32; ww++) tot[e] += wh[ww][e]; }
#pragma unroll
        for (int e = 0; e < 8; e++) {
            s_off[e] = s; g_off[e] = s; g_cnt[e] = tot[e]; ecnt[e] = (float)tot[e]; s += tot[e];
        }
    }
    __syncthreads();
    if (t < 256) {
        int e = t & 7, ww = t >> 3;
        int b = s_off[e];
        for (int wp = 0; wp < ww; wp++) b += wh[wp][e];
        wbase[ww][e] = b;
    }
    __syncthreads();

    // phase 2: warp-ballot allocation within each warp's token set
    int base0=wbase[w][0], base1=wbase[w][1], base2=wbase[w][2], base3=wbase[w][3];
    int base4=wbase[w][4], base5=wbase[w][5], base6=wbase[w][6], base7=wbase[w][7];
    int bases[8] = {base0,base1,base2,base3,base4,base5,base6,base7};
    const uint32_t ltm = (1u << lane) - 1u;
    for (int i = t; i < NTOK; i += 1024) {
        int b = i >> 12;
        int base = b * Tn + tok[i];
        int e0 = base & 7, e1 = (base + 1) & 7;
#pragma unroll
        for (int e = 0; e < 8; e++) {
            uint32_t m0 = __ballot_sync(0xFFFFFFFFu, e0 == e);
            if (e0 == e) g_rows[bases[e] + __popc(m0 & ltm)] = i;
            bases[e] += __popc(m0);
            uint32_t m1 = __ballot_sync(0xFFFFFFFFu, e1 == e);
            if (e1 == e) g_rows[bases[e] + __popc(m1 & ltm)] = i;
            bases[e] += __popc(m1);
        }
    }
}

// ---------------------------------------------------------------------------
// Other small kernels
// ---------------------------------------------------------------------------
__global__ void zero_out_kernel(float4* __restrict__ out4, int n4) {
    int i = blockIdx.x * blockDim.x + threadIdx.x;
    int stride = gridDim.x * blockDim.x;
    float4 z = make_float4(0.f, 0.f, 0.f, 0.f);
    for (; i < n4; i += stride) out4[i] = z;
}

__global__ void cvt_f16_kernel(const float4* __restrict__ in, __half2* __restrict__ out, int n4) {
    int i = blockIdx.x * blockDim.x + threadIdx.x;
    int stride = gridDim.x * blockDim.x;
    for (; i < n4; i += stride) {
        float4 v = in[i];
        out[2 * i]     = __floats2half2_rn(v.x, v.y);
        out[2 * i + 1] = __floats2half2_rn(v.z, v.w);
    }
}

__global__ void transpose_f16_kernel(const float* __restrict__ in, __half* __restrict__ out,
                                     int R, int C) {
    __shared__ float tile[32][33];
    int e = blockIdx.z;
    const float* src = in + (size_t)e * R * C;
    __half* dst = out + (size_t)e * R * C;
    int x = blockIdx.x * 32 + threadIdx.x;
#pragma unroll
    for (int i = threadIdx.y; i < 32; i += 8) {
        int y = blockIdx.y * 32 + i;
        tile[i][threadIdx.x] = src[(size_t)y * C + x];
    }
    __syncthreads();
    int xo = blockIdx.y * 32 + threadIdx.x;
#pragma unroll
    for (int i = threadIdx.y; i < 32; i += 8) {
        int yo = blockIdx.x * 32 + i;
        dst[(size_t)yo * R + xo] = __float2half_rn(tile[threadIdx.x][i]);
    }
}

// ---------------------------------------------------------------------------
// fp16 mma.sync grouped GEMM, 4-stage cp.async pipeline, ldmatrix fragments.
// Tile 128x128, BK=32, 256 threads = 8 warps (4m x 2n), warp tile 32x64.
// ---------------------------------------------------------------------------
#define TSTR   40
#define TILE_H (128 * TSTR)
#define NSTAGE 4
#define SMEM_BYTES (NSTAGE * 2 * TILE_H * 2)   /* 81920 B */

template <bool G1>
__global__ __launch_bounds__(256, 2) void moe_gemm_f16(
    const __half* __restrict__ Asrc,
    const __half* __restrict__ Bt,      // [E][N][K]
    const float*  __restrict__ bias,
    void*         __restrict__ outp)
{
    constexpr int KTOT  = G1 ? Dm : Ff;
    constexpr int NFULL = G1 ? Ff : Dm;
    constexpr int NC    = KTOT / 32;

    const int e   = blockIdx.z;
    const int cnt = g_cnt[e];
    const int m0  = blockIdx.y * 128;
    if (m0 >= cnt) return;
    const int off = g_off[e];
    const int n0  = blockIdx.x * 128;

    extern __shared__ __half sm[];
    __half* Asm = sm;                       // [NSTAGE][TILE_H]
    __half* Bsm = sm + NSTAGE * TILE_H;     // [NSTAGE][TILE_H]

    const int t = threadIdx.x;
    const int lane = t & 31, warp = t >> 5;
    const int wm = warp & 3, wn = warp >> 2;
    const int qr = lane >> 2, qc = lane & 3;

    // ---- gmem loaders ----
    const int lrow = t >> 2, lc8 = (t & 3) * 8;
    const __half* aptr[2];
#pragma unroll
    for (int it = 0; it < 2; it++) {
        int gi = m0 + it * 64 + lrow;
        if (gi >= cnt) gi = cnt - 1;
        size_t r = G1 ? (size_t)g_rows[off + gi] : (size_t)(off + gi);
        aptr[it] = Asrc + r * KTOT + lc8;
    }
    const __half* bptr[2];
#pragma unroll
    for (int it = 0; it < 2; it++)
        bptr[it] = Bt + ((size_t)e * NFULL + n0 + it * 64 + lrow) * KTOT + lc8;

    const uint32_t so = (uint32_t)(lrow * TSTR + lc8) * 2;
    const uint32_t a0 = smem_u32(Asm) + so;
    const uint32_t b0 = smem_u32(Bsm) + so;
    const uint32_t rowskip = 64 * TSTR * 2;

    auto load_chunk = [&](int c) {
        const uint32_t sbo = (uint32_t)(c & (NSTAGE - 1)) * (TILE_H * 2);
        const int k0 = c * 32;
        CP16(a0 + sbo,           aptr[0] + k0);
        CP16(a0 + sbo + rowskip, aptr[1] + k0);
        CP16(b0 + sbo,           bptr[0] + k0);
        CP16(b0 + sbo + rowskip, bptr[1] + k0);
        CP_COMMIT();
    };

    // ---- ldmatrix lane offsets (bytes, relative to tile base) ----
    // A x4 call fm: mat0=(rows,klo) mat1=(rows+8,klo) mat2=(rows,khi) mat3=(rows+8,khi)
    uint32_t aoff[2], boff[4];
#pragma unroll
    for (int fm = 0; fm < 2; fm++)
        aoff[fm] = (uint32_t)((wm * 32 + fm * 16 + ((lane >> 3) & 1) * 8 + (lane & 7)) * TSTR
                              + (lane >> 4) * 8) * 2;
    // B x4 call p: mat0=(n,klo) mat1=(n,khi) mat2=(n+8,klo) mat3=(n+8,khi)
#pragma unroll
    for (int p = 0; p < 4; p++)
        boff[p] = (uint32_t)((wn * 64 + p * 16 + (lane >> 4) * 8 + (lane & 7)) * TSTR
                             + ((lane >> 3) & 1) * 8) * 2;

    const uint32_t Abase0 = smem_u32(Asm);
    const uint32_t Bbase0 = smem_u32(Bsm);

    float acc[2][8][4];
#pragma unroll
    for (int fm = 0; fm < 2; fm++)
#pragma unroll
        for (int fn = 0; fn < 8; fn++)
#pragma unroll
            for (int q = 0; q < 4; q++) acc[fm][fn][q] = 0.f;

    load_chunk(0);
    load_chunk(1);
    load_chunk(2);

    for (int c = 0; c < NC; c++) {
        if (c <= NC - 3)      { CP_WAIT(2); }
        else if (c == NC - 2) { CP_WAIT(1); }
        else                  { CP_WAIT(0); }
        __syncthreads();
        if (c + 3 < NC) load_chunk(c + 3);

        const uint32_t sbo = (uint32_t)(c & (NSTAGE - 1)) * (TILE_H * 2);
        const uint32_t Ab = Abase0 + sbo;
        const uint32_t Bb = Bbase0 + sbo;

#pragma unroll
        for (int ks = 0; ks < 2; ks++) {
            const uint32_t kb = (uint32_t)ks * 32;   // 16 halves
            uint32_t a[2][4], b[8][2];
#pragma unroll
            for (int fm = 0; fm < 2; fm++)
                ldsm_x4(a[fm][0], a[fm][1], a[fm][2], a[fm][3], Ab + aoff[fm] + kb);
#pragma unroll
            for (int p = 0; p < 4; p++)
                ldsm_x4(b[2*p][0], b[2*p][1], b[2*p+1][0], b[2*p+1][1], Bb + boff[p] + kb);
#pragma unroll
            for (int fm = 0; fm < 2; fm++)
#pragma unroll
                for (int fn = 0; fn < 8; fn++)
                    mma_f16(acc[fm][fn], a[fm], b[fn]);
        }
    }

    // ---- epilogue (unchanged numerics) ----
#pragma unroll
    for (int fm = 0; fm < 2; fm++) {
#pragma unroll
        for (int rr = 0; rr < 2; rr++) {
            int m = m0 + wm * 32 + fm * 16 + rr * 8 + qr;
            if (m >= cnt) continue;
#pragma unroll
            for (int fn = 0; fn < 8; fn++) {
                int col = n0 + wn * 64 + fn * 8 + 2 * qc;
                float v0 = acc[fm][fn][rr * 2 + 0] + bias[e * NFULL + col];
                float v1 = acc[fm][fn][rr * 2 + 1] + bias[e * NFULL + col + 1];
                if (G1) {
                    __half* orow = (__half*)outp + (size_t)(off + m) * Ff;
                    float g0 = 0.5f * v0 * (1.0f + erff(v0 * 0.7071067811865476f));
                    float g1 = 0.5f * v1 * (1.0f + erff(v1 * 0.7071067811865476f));
                    *(__half2*)(orow + col) = __floats2half2_rn(g0, g1);
                } else {
                    float* orow = (float*)outp + (size_t)g_rows[off + m] * Dm;
                    atomicAdd(&orow[col],     0.25f * v0);
                    atomicAdd(&orow[col + 1], 0.25f * v1);
                }
            }
        }
    }
}

// ---------------------------------------------------------------------------
// Launch — gemm1 is the 4th kernel so ncu (-s 5 -c 1 empirically == launch #4)
// captures the GEMM instead of the routing kernel.
// ---------------------------------------------------------------------------
extern "C" void kernel_launch(void* const* d_in, const int* in_sizes, int n_in,
                              void* d_out, int out_size) {
    const float* x   = (const float*)d_in[0];
    const int*   tok = (const int*)d_in[1];
    const float* W1  = (const float*)d_in[2];
    const float* b1  = (const float*)d_in[3];
    const float* W2  = (const float*)d_in[4];
    const float* b2  = (const float*)d_in[5];

    float* out  = (float*)d_out;
    float* eid  = out + (size_t)NTOK * Dm;
    float* ecnt = eid + (size_t)NASG;

    static bool attr_set = false;
    if (!attr_set) {
        cudaFuncSetAttribute(moe_gemm_f16<true>,  cudaFuncAttributeMaxDynamicSharedMemorySize, SMEM_BYTES);
        cudaFuncSetAttribute(moe_gemm_f16<false>, cudaFuncAttributeMaxDynamicSharedMemorySize, SMEM_BYTES);
        attr_set = true;
    }

    __half* hbuf; cudaGetSymbolAddress((void**)&hbuf, g_h);
    __half* xh;   cudaGetSymbolAddress((void**)&xh,   g_xh);
    __half* w1t;  cudaGetSymbolAddress((void**)&w1t,  g_w1t);
    __half* w2t;  cudaGetSymbolAddress((void**)&w2t,  g_w2t);

    dim3 tb(32, 8);
    // 1: x -> fp16
    cvt_f16_kernel<<<1024, 256>>>((const float4*)x, (__half2*)xh, (NTOK * Dm) / 4);
    // 2: W1 -> W1^T fp16
    transpose_f16_kernel<<<dim3(Ff / 32, Dm / 32, Ee), tb>>>(W1, w1t, Dm, Ff);
    // 3: routing (ids, counts, offsets, gather lists)
    prep_kernel<<<1, 1024>>>(tok, eid, ecnt);
    // 4: GEMM1  <-- profiled launch
    dim3 g1(Ff / 128, 96, Ee);
    moe_gemm_f16<true><<<g1, 256, SMEM_BYTES>>>(xh, w1t, b1, (void*)hbuf);
    // 5: W2 -> W2^T fp16
    transpose_f16_kernel<<<dim3(Dm / 32, Ff / 32, Ee), tb>>>(W2, w2t, Ff, Dm);
    // 6: zero output
    zero_out_kernel<<<4096, 256>>>((float4*)out, (NTOK * Dm) / 4);
    // 7: GEMM2
    dim3 g2(Dm / 128, 96, Ee);
    moe_gemm_f16<false><<<g2, 256, SMEM_BYTES>>>(hbuf, w2t, b2, (void*)out);
}